// round 2
// baseline (speedup 1.0000x reference)
#include <cuda_runtime.h>
#include <cuda_bf16.h>
#include <math.h>

// Problem dims (fixed)
constexpr int CB   = 2;      // batch
constexpr int CL   = 1024;   // seq len
constexpr int CD   = 1024;   // d_model
constexpr int CDIN = 2048;   // d_inner
constexpr int CN   = 16;     // d_state
constexpr int CR   = 64;     // dt_rank
constexpr int CK   = 4;      // conv width
constexpr int CML  = CB * CL;       // 2048 rows
constexpr float CLN_EPS = 1e-5f;

// ---------------- scratch (device globals; no allocation) ----------------
__device__ float g_xz   [CML * (2*CDIN)];      // [2048, 4096]  (x_in | z)
__device__ float g_xc   [CML * CDIN];          // [2048, 2048]  conv+silu
__device__ float g_xdbl [CML * (CR + 2*CN)];   // [2048, 96]
__device__ float g_delta[CML * CDIN];          // [2048, 2048]
__device__ float g_yg   [CML * CDIN];          // [2048, 2048]  gated scan output
__device__ float g_pre  [CML * CD];            // [2048, 1024]  pre-layernorm

// ---------------- generic fp32 SGEMM: C[M,N] = A[M,K] * B[K,N] ----------------
// BM=BN=128, BK=8, 256 threads, 8x8 per thread.
// EPI: 0 = plain store, 1 = softplus(acc + bias[col])
template<int EPI>
__global__ __launch_bounds__(256)
void sgemm_kernel(int M, int N, int K,
                  const float* __restrict__ A, int lda,
                  const float* __restrict__ Bm, int ldb,
                  float* __restrict__ C, int ldc,
                  const float* __restrict__ bias)
{
    const int BM = 128, BN = 128, BK = 8, TM = 8, TN = 8;
    __shared__ float As[BK][BM];
    __shared__ float Bs[BK][BN];

    int tid = threadIdx.x;
    int row0 = blockIdx.y * BM;
    int col0 = blockIdx.x * BN;

    int tx = tid & 15;        // 0..15
    int ty = tid >> 4;        // 0..15

    // A tile load: 128 rows x 8 k; each thread loads float4 along K
    int aRow = tid >> 1;            // 0..127
    int aK   = (tid & 1) * 4;       // 0 or 4
    // B tile load: 8 k-rows x 128 cols; each thread loads float4 along N
    int bRow = tid >> 5;            // 0..7
    int bCol = (tid & 31) * 4;      // 0..124

    float acc[TM][TN];
    #pragma unroll
    for (int i = 0; i < TM; i++)
        #pragma unroll
        for (int j = 0; j < TN; j++) acc[i][j] = 0.f;

    for (int k0 = 0; k0 < K; k0 += BK) {
        // load A tile (M multiple of 128, K multiple of 8 -> no guards)
        {
            const float* ap = A + (size_t)(row0 + aRow) * lda + (k0 + aK);
            float4 av = *reinterpret_cast<const float4*>(ap);
            As[aK + 0][aRow] = av.x;
            As[aK + 1][aRow] = av.y;
            As[aK + 2][aRow] = av.z;
            As[aK + 3][aRow] = av.w;
        }
        // load B tile with N guard (for N=96 case)
        {
            int gcol = col0 + bCol;
            float4 bv;
            if (gcol + 3 < N) {
                bv = *reinterpret_cast<const float4*>(Bm + (size_t)(k0 + bRow) * ldb + gcol);
            } else {
                bv.x = (gcol + 0 < N) ? Bm[(size_t)(k0 + bRow) * ldb + gcol + 0] : 0.f;
                bv.y = (gcol + 1 < N) ? Bm[(size_t)(k0 + bRow) * ldb + gcol + 1] : 0.f;
                bv.z = (gcol + 2 < N) ? Bm[(size_t)(k0 + bRow) * ldb + gcol + 2] : 0.f;
                bv.w = (gcol + 3 < N) ? Bm[(size_t)(k0 + bRow) * ldb + gcol + 3] : 0.f;
            }
            *reinterpret_cast<float4*>(&Bs[bRow][bCol]) = bv;
        }
        __syncthreads();

        #pragma unroll
        for (int kk = 0; kk < BK; kk++) {
            float ra[TM], rb[TN];
            #pragma unroll
            for (int i = 0; i < TM; i++) ra[i] = As[kk][ty * TM + i];
            #pragma unroll
            for (int j = 0; j < TN; j++) rb[j] = Bs[kk][tx * TN + j];
            #pragma unroll
            for (int i = 0; i < TM; i++)
                #pragma unroll
                for (int j = 0; j < TN; j++)
                    acc[i][j] = fmaf(ra[i], rb[j], acc[i][j]);
        }
        __syncthreads();
    }

    // store
    #pragma unroll
    for (int i = 0; i < TM; i++) {
        int r = row0 + ty * TM + i;
        #pragma unroll
        for (int j = 0; j < TN; j++) {
            int c = col0 + tx * TN + j;
            if (c < N) {
                float v = acc[i][j];
                if (EPI == 1) {
                    v = v + bias[c];
                    // stable softplus
                    v = (v > 20.f) ? v : log1pf(__expf(v));
                }
                C[(size_t)r * ldc + c] = v;
            }
        }
    }
}

// ---------------- causal depthwise conv (K=4) + SiLU ----------------
__global__ void conv_silu_kernel(const float* __restrict__ conv_w,
                                 const float* __restrict__ conv_b)
{
    int i = blockIdx.x * blockDim.x + threadIdx.x;   // over CML*CDIN
    if (i >= CML * CDIN) return;
    int d  = i & (CDIN - 1);
    int bl = i >> 11;          // i / CDIN
    int l  = bl & (CL - 1);
    int b  = bl >> 10;

    float acc = conv_b[d];
    #pragma unroll
    for (int k = 0; k < CK; k++) {
        int ll = l - (CK - 1) + k;
        if (ll >= 0) {
            float xin = g_xz[(size_t)(b * CL + ll) * (2 * CDIN) + d];
            acc = fmaf(xin, conv_w[d * CK + k], acc);
        }
    }
    // SiLU
    float sig = 1.f / (1.f + __expf(-acc));
    g_xc[i] = acc * sig;
}

// ---------------- selective scan (warp = 2 channels, 16 states/lane-group) ----------------
// fused with skip + gating: yg = (scan_y + xc*D) * silu(z)
__global__ __launch_bounds__(128)
void scan_kernel(const float* __restrict__ A_log,
                 const float* __restrict__ D_skip)
{
    int warp = (blockIdx.x * blockDim.x + threadIdx.x) >> 5;  // 0..2047
    int lane = threadIdx.x & 31;
    int half = lane >> 4;          // 0/1 -> which channel of the pair
    int n    = lane & 15;          // state index

    int b = warp >> 10;                       // 0/1
    int d = ((warp & 1023) << 1) + half;      // 0..2047

    float a_coef = -expf(A_log[d * CN + n]);  // A[d][n]
    float d_skip = D_skip[d];
    float h  = 0.f;

    const size_t bl0 = (size_t)b * CL;
    for (int t = 0; t < CL; t++) {
        size_t bl = bl0 + t;
        float dv = g_delta[bl * CDIN + d];
        float xc = g_xc   [bl * CDIN + d];
        float Bn = g_xdbl [bl * 96 + CR + n];
        float Cn = g_xdbl [bl * 96 + CR + CN + n];

        float dA = __expf(dv * a_coef);
        h = fmaf(dA, h, dv * Bn * xc);

        float v = h * Cn;
        v += __shfl_xor_sync(0xffffffffu, v, 8);
        v += __shfl_xor_sync(0xffffffffu, v, 4);
        v += __shfl_xor_sync(0xffffffffu, v, 2);
        v += __shfl_xor_sync(0xffffffffu, v, 1);

        if (n == 0) {
            float zv = g_xz[bl * (2 * CDIN) + CDIN + d];
            float yv = v + xc * d_skip;
            float sig = 1.f / (1.f + __expf(-zv));
            g_yg[bl * CDIN + d] = yv * (zv * sig);
        }
    }
}

// ---------------- LayerNorm over last dim (1024) ----------------
__global__ __launch_bounds__(256)
void ln_kernel(const float* __restrict__ gamma,
               const float* __restrict__ beta,
               float* __restrict__ out)
{
    int row = blockIdx.x;                // 0..2047
    const float* p = g_pre + (size_t)row * CD;
    int tid = threadIdx.x;

    float s = 0.f, s2 = 0.f;
    for (int c = tid; c < CD; c += 256) {
        float v = p[c];
        s  += v;
        s2 += v * v;
    }
    // warp reduce
    #pragma unroll
    for (int o = 16; o >= 1; o >>= 1) {
        s  += __shfl_xor_sync(0xffffffffu, s,  o);
        s2 += __shfl_xor_sync(0xffffffffu, s2, o);
    }
    __shared__ float shs[8], shs2[8];
    int wid = tid >> 5;
    if ((tid & 31) == 0) { shs[wid] = s; shs2[wid] = s2; }
    __syncthreads();
    if (tid < 32) {
        s  = (tid < 8) ? shs[tid]  : 0.f;
        s2 = (tid < 8) ? shs2[tid] : 0.f;
        #pragma unroll
        for (int o = 4; o >= 1; o >>= 1) {
            s  += __shfl_xor_sync(0xffffffffu, s,  o);
            s2 += __shfl_xor_sync(0xffffffffu, s2, o);
        }
        if (tid == 0) { shs[0] = s; shs2[0] = s2; }
    }
    __syncthreads();
    float mean = shs[0] * (1.f / CD);
    float var  = shs2[0] * (1.f / CD) - mean * mean;
    float rstd = rsqrtf(var + CLN_EPS);

    for (int c = tid; c < CD; c += 256) {
        float v = p[c];
        out[(size_t)row * CD + c] = (v - mean) * rstd * gamma[c] + beta[c];
    }
}

// ---------------- launch ----------------
extern "C" void kernel_launch(void* const* d_in, const int* in_sizes, int n_in,
                              void* d_out, int out_size)
{
    const float* x      = (const float*)d_in[0];   // [2,1024,1024]
    const float* W_in   = (const float*)d_in[1];   // [1024,4096]
    const float* conv_w = (const float*)d_in[2];   // [2048,4]
    const float* conv_b = (const float*)d_in[3];   // [2048]
    const float* W_x    = (const float*)d_in[4];   // [2048,96]
    const float* W_dt   = (const float*)d_in[5];   // [64,2048]
    const float* b_dt   = (const float*)d_in[6];   // [2048]
    const float* A_log  = (const float*)d_in[7];   // [2048,16]
    const float* D_skip = (const float*)d_in[8];   // [2048]
    const float* W_out  = (const float*)d_in[9];   // [2048,1024]
    const float* ln_g   = (const float*)d_in[10];  // [1024]
    const float* ln_b   = (const float*)d_in[11];  // [1024]
    float* out = (float*)d_out;

    float *p_xz, *p_xc, *p_xdbl, *p_delta, *p_yg, *p_pre;
    cudaGetSymbolAddress((void**)&p_xz,   g_xz);
    cudaGetSymbolAddress((void**)&p_xc,   g_xc);
    cudaGetSymbolAddress((void**)&p_xdbl, g_xdbl);
    cudaGetSymbolAddress((void**)&p_delta,g_delta);
    cudaGetSymbolAddress((void**)&p_yg,   g_yg);
    cudaGetSymbolAddress((void**)&p_pre,  g_pre);

    dim3 thr(256);

    // G1: xz = x @ W_in   [2048,1024]x[1024,4096]
    sgemm_kernel<0><<<dim3((2*CDIN)/128, CML/128), thr>>>(
        CML, 2*CDIN, CD, x, CD, W_in, 2*CDIN, p_xz, 2*CDIN, nullptr);

    // conv + silu
    conv_silu_kernel<<<(CML*CDIN + 255)/256, 256>>>(conv_w, conv_b);

    // G2: x_dbl = x_conv @ W_x   [2048,2048]x[2048,96]
    sgemm_kernel<0><<<dim3(1, CML/128), thr>>>(
        CML, CR + 2*CN, CDIN, p_xc, CDIN, W_x, CR + 2*CN, p_xdbl, CR + 2*CN, nullptr);

    // G3: delta = softplus(dt @ W_dt + b_dt)   [2048,64]x[64,2048]
    sgemm_kernel<1><<<dim3(CDIN/128, CML/128), thr>>>(
        CML, CDIN, CR, p_xdbl, CR + 2*CN, W_dt, CDIN, p_delta, CDIN, b_dt);

    // scan (+ skip + gate)
    scan_kernel<<<(CB*CDIN/2)*32/128, 128>>>(A_log, D_skip);

    // G4: pre = yg @ W_out   [2048,2048]x[2048,1024]
    sgemm_kernel<0><<<dim3(CD/128, CML/128), thr>>>(
        CML, CD, CDIN, p_yg, CDIN, W_out, CD, p_pre, CD, nullptr);

    // LayerNorm
    ln_kernel<<<CML, 256>>>(ln_g, ln_b, out);
}

// round 3
// speedup vs baseline: 1.1912x; 1.1912x over previous
#include <cuda_runtime.h>
#include <cuda_bf16.h>
#include <math.h>
#include <stdint.h>

// Problem dims (fixed)
constexpr int CB   = 2;      // batch
constexpr int CL   = 1024;   // seq len
constexpr int CD   = 1024;   // d_model
constexpr int CDIN = 2048;   // d_inner
constexpr int CN   = 16;     // d_state
constexpr int CR   = 64;     // dt_rank
constexpr int CK   = 4;      // conv width
constexpr int CML  = CB * CL;       // 2048 rows
constexpr float CLN_EPS = 1e-5f;

// ---------------- scratch (device globals; no allocation) ----------------
__device__ float g_xz   [CML * (2*CDIN)];      // [2048, 4096]  (x_in | z)
__device__ float g_xc   [CML * CDIN];          // [2048, 2048]  conv+silu
__device__ float g_xdbl [CML * (CR + 2*CN)];   // [2048, 96]
__device__ float g_delta[CML * CDIN];          // [2048, 2048]
__device__ float g_yg   [CML * CDIN];          // [2048, 2048]  gated scan output
__device__ float g_pre  [CML * CD];            // [2048, 1024]  pre-layernorm

// ---------------- helpers ----------------
__device__ __forceinline__ void split_tf32(float x, uint32_t& hi, uint32_t& lo)
{
    uint32_t h;
    asm("cvt.rna.tf32.f32 %0, %1;" : "=r"(h) : "f"(x));
    float hf = __uint_as_float(h);
    float lf = x - hf;
    uint32_t l;
    asm("cvt.rna.tf32.f32 %0, %1;" : "=r"(l) : "f"(lf));
    hi = h; lo = l;
}

__device__ __forceinline__ void mma_tf32(float* acc, const uint32_t* a, const uint32_t* b)
{
    asm volatile(
        "mma.sync.aligned.m16n8k8.row.col.f32.tf32.tf32.f32 "
        "{%0,%1,%2,%3}, {%4,%5,%6,%7}, {%8,%9}, {%0,%1,%2,%3};\n"
        : "+f"(acc[0]), "+f"(acc[1]), "+f"(acc[2]), "+f"(acc[3])
        : "r"(a[0]), "r"(a[1]), "r"(a[2]), "r"(a[3]), "r"(b[0]), "r"(b[1]));
}

// ---------------- TF32-split tensor-core GEMM ----------------
// C[M,N] = A[M,K] @ B[K,N], fp32 in/out, ~fp32 accuracy via 3-term tf32 split.
// BM=BN=128, BK=16, 256 threads = 8 warps (2 x 4), warp tile 64x32.
// Requirements: M % 128 == 0, K % 16 == 0. N guarded.
// EPI: 0 = plain store, 1 = softplus(acc + bias[col])
template<int EPI>
__global__ __launch_bounds__(256)
void tgemm_kernel(int M, int N, int K,
                  const float* __restrict__ A, int lda,
                  const float* __restrict__ Bm, int ldb,
                  float* __restrict__ C, int ldc,
                  const float* __restrict__ bias)
{
    constexpr int BM = 128, BN = 128, BK = 16;
    constexpr int APAD = 4;    // stride 20 -> conflict-free A frag loads
    constexpr int BPAD = 4;    // stride 132 -> ~2-way on B frag loads (ok)

    __shared__ float Ah[BM][BK + APAD];
    __shared__ float Al[BM][BK + APAD];
    __shared__ float Bh[BK][BN + BPAD];
    __shared__ float Bl[BK][BN + BPAD];

    const int tid  = threadIdx.x;
    const int warp = tid >> 5;
    const int lane = tid & 31;
    const int g    = lane >> 2;   // group id 0..7
    const int tg   = lane & 3;    // thread in group 0..3

    const int row0 = blockIdx.y * BM;
    const int col0 = blockIdx.x * BN;

    // warp tile origin within block
    const int wm0 = (warp >> 2) * 64;   // 0 or 64
    const int wn0 = (warp & 3) * 32;    // 0,32,64,96

    // A cooperative load: thread -> row tid>>1, col (tid&1)*8 (+0..7)
    const int aRow = tid >> 1;
    const int aCol = (tid & 1) * 8;
    // B cooperative load: thread -> row tid>>4, col (tid&15)*8 (+0..7)
    const int bRow = tid >> 4;
    const int bCol = (tid & 15) * 8;

    float acc[4][4][4];   // [mt][nt][4]
    #pragma unroll
    for (int i = 0; i < 4; i++)
        #pragma unroll
        for (int j = 0; j < 4; j++)
            #pragma unroll
            for (int r = 0; r < 4; r++) acc[i][j][r] = 0.f;

    for (int k0 = 0; k0 < K; k0 += BK) {
        // ---- load + split A tile ----
        {
            const float* ap = A + (size_t)(row0 + aRow) * lda + (k0 + aCol);
            float4 v0 = *reinterpret_cast<const float4*>(ap);
            float4 v1 = *reinterpret_cast<const float4*>(ap + 4);
            float vv[8] = {v0.x, v0.y, v0.z, v0.w, v1.x, v1.y, v1.z, v1.w};
            #pragma unroll
            for (int i = 0; i < 8; i++) {
                uint32_t h, l;
                split_tf32(vv[i], h, l);
                Ah[aRow][aCol + i] = __uint_as_float(h);
                Al[aRow][aCol + i] = __uint_as_float(l);
            }
        }
        // ---- load + split B tile (N-guarded) ----
        {
            const int gcol = col0 + bCol;
            float vv[8];
            if (gcol + 7 < N) {
                const float* bp = Bm + (size_t)(k0 + bRow) * ldb + gcol;
                float4 v0 = *reinterpret_cast<const float4*>(bp);
                float4 v1 = *reinterpret_cast<const float4*>(bp + 4);
                vv[0]=v0.x; vv[1]=v0.y; vv[2]=v0.z; vv[3]=v0.w;
                vv[4]=v1.x; vv[5]=v1.y; vv[6]=v1.z; vv[7]=v1.w;
            } else {
                #pragma unroll
                for (int i = 0; i < 8; i++)
                    vv[i] = (gcol + i < N) ? Bm[(size_t)(k0 + bRow) * ldb + gcol + i] : 0.f;
            }
            #pragma unroll
            for (int i = 0; i < 8; i++) {
                uint32_t h, l;
                split_tf32(vv[i], h, l);
                Bh[bRow][bCol + i] = __uint_as_float(h);
                Bl[bRow][bCol + i] = __uint_as_float(l);
            }
        }
        __syncthreads();

        // ---- two k8 sub-steps ----
        #pragma unroll
        for (int ks = 0; ks < BK; ks += 8) {
            uint32_t afh[4][4], afl[4][4];
            #pragma unroll
            for (int mt = 0; mt < 4; mt++) {
                int r = wm0 + mt * 16 + g;
                afh[mt][0] = __float_as_uint(Ah[r    ][ks + tg    ]);
                afh[mt][1] = __float_as_uint(Ah[r + 8][ks + tg    ]);
                afh[mt][2] = __float_as_uint(Ah[r    ][ks + tg + 4]);
                afh[mt][3] = __float_as_uint(Ah[r + 8][ks + tg + 4]);
                afl[mt][0] = __float_as_uint(Al[r    ][ks + tg    ]);
                afl[mt][1] = __float_as_uint(Al[r + 8][ks + tg    ]);
                afl[mt][2] = __float_as_uint(Al[r    ][ks + tg + 4]);
                afl[mt][3] = __float_as_uint(Al[r + 8][ks + tg + 4]);
            }
            uint32_t bfh[4][2], bfl[4][2];
            #pragma unroll
            for (int nt = 0; nt < 4; nt++) {
                int c = wn0 + nt * 8 + g;
                bfh[nt][0] = __float_as_uint(Bh[ks + tg    ][c]);
                bfh[nt][1] = __float_as_uint(Bh[ks + tg + 4][c]);
                bfl[nt][0] = __float_as_uint(Bl[ks + tg    ][c]);
                bfl[nt][1] = __float_as_uint(Bl[ks + tg + 4][c]);
            }
            #pragma unroll
            for (int mt = 0; mt < 4; mt++)
                #pragma unroll
                for (int nt = 0; nt < 4; nt++) {
                    mma_tf32(acc[mt][nt], afh[mt], bfh[nt]);   // hi*hi
                    mma_tf32(acc[mt][nt], afh[mt], bfl[nt]);   // hi*lo
                    mma_tf32(acc[mt][nt], afl[mt], bfh[nt]);   // lo*hi
                }
        }
        __syncthreads();
    }

    // ---- store ----
    #pragma unroll
    for (int mt = 0; mt < 4; mt++) {
        int r0 = row0 + wm0 + mt * 16 + g;
        #pragma unroll
        for (int nt = 0; nt < 4; nt++) {
            int c0 = col0 + wn0 + nt * 8 + 2 * tg;
            #pragma unroll
            for (int rr = 0; rr < 2; rr++) {
                int r = r0 + rr * 8;
                #pragma unroll
                for (int cc = 0; cc < 2; cc++) {
                    int c = c0 + cc;
                    if (c < N) {
                        float v = acc[mt][nt][rr * 2 + cc];
                        if (EPI == 1) {
                            v = v + bias[c];
                            v = (v > 20.f) ? v : log1pf(__expf(v));
                        }
                        C[(size_t)r * ldc + c] = v;
                    }
                }
            }
        }
    }
}

// ---------------- causal depthwise conv (K=4) + SiLU ----------------
__global__ void conv_silu_kernel(const float* __restrict__ conv_w,
                                 const float* __restrict__ conv_b)
{
    int i = blockIdx.x * blockDim.x + threadIdx.x;   // over CML*CDIN
    if (i >= CML * CDIN) return;
    int d  = i & (CDIN - 1);
    int bl = i >> 11;          // i / CDIN
    int l  = bl & (CL - 1);
    int b  = bl >> 10;

    float acc = conv_b[d];
    #pragma unroll
    for (int k = 0; k < CK; k++) {
        int ll = l - (CK - 1) + k;
        if (ll >= 0) {
            float xin = g_xz[(size_t)(b * CL + ll) * (2 * CDIN) + d];
            acc = fmaf(xin, conv_w[d * CK + k], acc);
        }
    }
    float sig = 1.f / (1.f + __expf(-acc));
    g_xc[i] = acc * sig;
}

// ---------------- selective scan (warp = 2 channels, 16 states/lane-group) ----------------
__global__ __launch_bounds__(128)
void scan_kernel(const float* __restrict__ A_log,
                 const float* __restrict__ D_skip)
{
    int warp = (blockIdx.x * blockDim.x + threadIdx.x) >> 5;  // 0..2047
    int lane = threadIdx.x & 31;
    int half = lane >> 4;
    int n    = lane & 15;

    int b = warp >> 10;
    int d = ((warp & 1023) << 1) + half;

    float a_coef = -expf(A_log[d * CN + n]);
    float d_skip = D_skip[d];
    float h  = 0.f;

    const size_t bl0 = (size_t)b * CL;
    for (int t = 0; t < CL; t++) {
        size_t bl = bl0 + t;
        float dv = g_delta[bl * CDIN + d];
        float xc = g_xc   [bl * CDIN + d];
        float Bn = g_xdbl [bl * 96 + CR + n];
        float Cn = g_xdbl [bl * 96 + CR + CN + n];

        float dA = __expf(dv * a_coef);
        h = fmaf(dA, h, dv * Bn * xc);

        float v = h * Cn;
        v += __shfl_xor_sync(0xffffffffu, v, 8);
        v += __shfl_xor_sync(0xffffffffu, v, 4);
        v += __shfl_xor_sync(0xffffffffu, v, 2);
        v += __shfl_xor_sync(0xffffffffu, v, 1);

        if (n == 0) {
            float zv = g_xz[bl * (2 * CDIN) + CDIN + d];
            float yv = v + xc * d_skip;
            float sig = 1.f / (1.f + __expf(-zv));
            g_yg[bl * CDIN + d] = yv * (zv * sig);
        }
    }
}

// ---------------- LayerNorm over last dim (1024) ----------------
__global__ __launch_bounds__(256)
void ln_kernel(const float* __restrict__ gamma,
               const float* __restrict__ beta,
               float* __restrict__ out)
{
    int row = blockIdx.x;
    const float* p = g_pre + (size_t)row * CD;
    int tid = threadIdx.x;

    float s = 0.f, s2 = 0.f;
    for (int c = tid; c < CD; c += 256) {
        float v = p[c];
        s  += v;
        s2 += v * v;
    }
    #pragma unroll
    for (int o = 16; o >= 1; o >>= 1) {
        s  += __shfl_xor_sync(0xffffffffu, s,  o);
        s2 += __shfl_xor_sync(0xffffffffu, s2, o);
    }
    __shared__ float shs[8], shs2[8];
    int wid = tid >> 5;
    if ((tid & 31) == 0) { shs[wid] = s; shs2[wid] = s2; }
    __syncthreads();
    if (tid < 32) {
        s  = (tid < 8) ? shs[tid]  : 0.f;
        s2 = (tid < 8) ? shs2[tid] : 0.f;
        #pragma unroll
        for (int o = 4; o >= 1; o >>= 1) {
            s  += __shfl_xor_sync(0xffffffffu, s,  o);
            s2 += __shfl_xor_sync(0xffffffffu, s2, o);
        }
        if (tid == 0) { shs[0] = s; shs2[0] = s2; }
    }
    __syncthreads();
    float mean = shs[0] * (1.f / CD);
    float var  = shs2[0] * (1.f / CD) - mean * mean;
    float rstd = rsqrtf(var + CLN_EPS);

    for (int c = tid; c < CD; c += 256) {
        float v = p[c];
        out[(size_t)row * CD + c] = (v - mean) * rstd * gamma[c] + beta[c];
    }
}

// ---------------- launch ----------------
extern "C" void kernel_launch(void* const* d_in, const int* in_sizes, int n_in,
                              void* d_out, int out_size)
{
    const float* x      = (const float*)d_in[0];   // [2,1024,1024]
    const float* W_in   = (const float*)d_in[1];   // [1024,4096]
    const float* conv_w = (const float*)d_in[2];   // [2048,4]
    const float* conv_b = (const float*)d_in[3];   // [2048]
    const float* W_x    = (const float*)d_in[4];   // [2048,96]
    const float* W_dt   = (const float*)d_in[5];   // [64,2048]
    const float* b_dt   = (const float*)d_in[6];   // [2048]
    const float* A_log  = (const float*)d_in[7];   // [2048,16]
    const float* D_skip = (const float*)d_in[8];   // [2048]
    const float* W_out  = (const float*)d_in[9];   // [2048,1024]
    const float* ln_g   = (const float*)d_in[10];  // [1024]
    const float* ln_b   = (const float*)d_in[11];  // [1024]
    float* out = (float*)d_out;

    float *p_xz, *p_xc, *p_xdbl, *p_delta, *p_yg, *p_pre;
    cudaGetSymbolAddress((void**)&p_xz,   g_xz);
    cudaGetSymbolAddress((void**)&p_xc,   g_xc);
    cudaGetSymbolAddress((void**)&p_xdbl, g_xdbl);
    cudaGetSymbolAddress((void**)&p_delta,g_delta);
    cudaGetSymbolAddress((void**)&p_yg,   g_yg);
    cudaGetSymbolAddress((void**)&p_pre,  g_pre);

    dim3 thr(256);

    // G1: xz = x @ W_in   [2048,1024]x[1024,4096]
    tgemm_kernel<0><<<dim3((2*CDIN)/128, CML/128), thr>>>(
        CML, 2*CDIN, CD, x, CD, W_in, 2*CDIN, p_xz, 2*CDIN, nullptr);

    // conv + silu
    conv_silu_kernel<<<(CML*CDIN + 255)/256, 256>>>(conv_w, conv_b);

    // G2: x_dbl = x_conv @ W_x   [2048,2048]x[2048,96]
    tgemm_kernel<0><<<dim3(1, CML/128), thr>>>(
        CML, CR + 2*CN, CDIN, p_xc, CDIN, W_x, CR + 2*CN, p_xdbl, CR + 2*CN, nullptr);

    // G3: delta = softplus(dt @ W_dt + b_dt)   [2048,64]x[64,2048]
    tgemm_kernel<1><<<dim3(CDIN/128, CML/128), thr>>>(
        CML, CDIN, CR, p_xdbl, CR + 2*CN, W_dt, CDIN, p_delta, CDIN, b_dt);

    // scan (+ skip + gate)
    scan_kernel<<<(CB*CDIN/2)*32/128, 128>>>(A_log, D_skip);

    // G4: pre = yg @ W_out   [2048,2048]x[2048,1024]
    tgemm_kernel<0><<<dim3(CD/128, CML/128), thr>>>(
        CML, CD, CDIN, p_yg, CDIN, W_out, CD, p_pre, CD, nullptr);

    // LayerNorm
    ln_kernel<<<CML, 256>>>(ln_g, ln_b, out);
}